// round 15
// baseline (speedup 1.0000x reference)
#include <cuda_runtime.h>
#include <cuda_fp16.h>
#include <math.h>
#include <stdint.h>

#define HEADS 8
#define DIM 128
#define INC 128
#define EPS 1e-5f
#define QSCALE 0.08838834764831845f   // 128^-0.5
#define LOG2E  1.4426950408889634f

typedef unsigned long long ull;

__device__ float g_qkv[2048 * 32768];   // [b][h][r(0..31)][d]

__device__ __forceinline__ ull pk2(float a, float b) {
    ull r; asm("mov.b64 %0, {%1, %2};" : "=l"(r) : "f"(a), "f"(b)); return r;
}
__device__ __forceinline__ void upk2(ull v, float& a, float& b) {
    asm("mov.b64 {%0, %1}, %2;" : "=f"(a), "=f"(b) : "l"(v));
}
__device__ __forceinline__ ull fma2(ull a, ull b, ull c) {
    ull r; asm("fma.rn.f32x2 %0, %1, %2, %3;" : "=l"(r) : "l"(a), "l"(b), "l"(c));
    return r;
}
__device__ __forceinline__ ull add2(ull a, ull b) {
    ull r; asm("add.rn.f32x2 %0, %1, %2;" : "=l"(r) : "l"(a), "l"(b));
    return r;
}
__device__ __forceinline__ uint32_t f2tf32(float f) {
    uint32_t r; asm("cvt.rna.tf32.f32 %0, %1;" : "=r"(r) : "f"(f)); return r;
}
__device__ __forceinline__ float ex2f(float x) {
    float r; asm("ex2.approx.ftz.f32 %0, %1;" : "=f"(r) : "f"(x)); return r;
}
__device__ __forceinline__ void mma_tf32(float* c, const uint32_t* a, const uint32_t* b) {
    asm volatile(
        "mma.sync.aligned.m16n8k8.row.col.f32.tf32.tf32.f32 "
        "{%0,%1,%2,%3}, {%4,%5,%6,%7}, {%8,%9}, {%0,%1,%2,%3};"
        : "+f"(c[0]), "+f"(c[1]), "+f"(c[2]), "+f"(c[3])
        : "r"(a[0]), "r"(a[1]), "r"(a[2]), "r"(a[3]), "r"(b[0]), "r"(b[1]));
}
__device__ __forceinline__ void mma_f16(float* c, const uint32_t* a, const uint32_t* b) {
    asm volatile(
        "mma.sync.aligned.m16n8k16.row.col.f32.f16.f16.f32 "
        "{%0,%1,%2,%3}, {%4,%5,%6,%7}, {%8,%9}, {%0,%1,%2,%3};"
        : "+f"(c[0]), "+f"(c[1]), "+f"(c[2]), "+f"(c[3])
        : "r"(a[0]), "r"(a[1]), "r"(a[2]), "r"(a[3]), "r"(b[0]), "r"(b[1]));
}
__device__ __forceinline__ void ldsm_x4_t(uint32_t& r0, uint32_t& r1,
                                          uint32_t& r2, uint32_t& r3, uint32_t addr) {
    asm volatile("ldmatrix.sync.aligned.m8n8.x4.trans.shared.b16 {%0,%1,%2,%3}, [%4];"
                 : "=r"(r0), "=r"(r1), "=r"(r2), "=r"(r3) : "r"(addr));
}
__device__ __forceinline__ void ldsm_x2(uint32_t& r0, uint32_t& r1, uint32_t addr) {
    asm volatile("ldmatrix.sync.aligned.m8n8.x2.shared.b16 {%0,%1}, [%2];"
                 : "=r"(r0), "=r"(r1) : "r"(addr));
}
__device__ __forceinline__ uint32_t smem_u32(const void* p) {
    uint32_t a;
    asm("{ .reg .u64 t; cvta.to.shared.u64 t, %1; cvt.u32.u64 %0, t; }"
        : "=r"(a) : "l"(p));
    return a;
}

// ============================================================================
// Kernel A: conv1x1 + BN via mma.sync tf32 (verified) — q rows also x LOG2E
// ============================================================================
#define CA_STR 132
#define CB_STR 136
#define CV_BS  (128 * CA_STR)
#define CV_IV  (CV_BS + 128 * CB_STR)
#define CV_BB  (CV_IV + 128)
#define CV_TOT (CV_BB + 128)

__global__ void __launch_bounds__(512, 1)
conv_bn_mma_kernel(const float* __restrict__ x, const float* __restrict__ W,
                   const float* __restrict__ gamma, const float* __restrict__ beta,
                   const float* __restrict__ mean, const float* __restrict__ var,
                   float* __restrict__ qkv)
{
    extern __shared__ float sm[];
    float* As  = sm;
    float* Bs  = sm + CV_BS;
    float* ivs = sm + CV_IV;
    float* bss = sm + CV_BB;

    const int t      = threadIdx.x;
    const int b      = blockIdx.x >> 1;
    const int o_base = (blockIdx.x & 1) * 128;

#pragma unroll
    for (int it = 0; it < 8; ++it) {
        int e  = t + 512 * it;
        int o  = e >> 5;
        int c4 = (e & 31) * 4;
        float4 wv = *reinterpret_cast<const float4*>(W + (o_base + o) * 128 + c4);
        float4 s;
        s.x = __uint_as_float(f2tf32(wv.x));
        s.y = __uint_as_float(f2tf32(wv.y));
        s.z = __uint_as_float(f2tf32(wv.z));
        s.w = __uint_as_float(f2tf32(wv.w));
        *reinterpret_cast<float4*>(As + o * CA_STR + c4) = s;
    }
#pragma unroll
    for (int it = 0; it < 8; ++it) {
        int e  = t + 512 * it;
        int c  = e >> 5;
        int d4 = (e & 31) * 4;
        float4 xv = *reinterpret_cast<const float4*>(x + (size_t)b * 16384 + c * 128 + d4);
        float4 s;
        s.x = __uint_as_float(f2tf32(xv.x));
        s.y = __uint_as_float(f2tf32(xv.y));
        s.z = __uint_as_float(f2tf32(xv.z));
        s.w = __uint_as_float(f2tf32(xv.w));
        *reinterpret_cast<float4*>(Bs + c * CB_STR + d4) = s;
    }
    if (t < 128) {
        int o = o_base + t;
        float iv   = gamma[o] * rsqrtf(var[o] + EPS);
        float bias = beta[o] - mean[o] * iv;
        if (o < 64) { iv *= QSCALE * LOG2E; bias *= QSCALE * LOG2E; }
        ivs[t] = iv;
        bss[t] = bias;
    }
    __syncthreads();

    const int warp = t >> 5, lane = t & 31;
    const int wm = warp & 3, wn = warp >> 2;
    const int m0 = wm * 32, n0 = wn * 32;
    const int gp = lane >> 2, tid4 = lane & 3;

    float acc[8][4];
#pragma unroll
    for (int i = 0; i < 8; ++i)
#pragma unroll
        for (int p = 0; p < 4; ++p) acc[i][p] = 0.f;

#pragma unroll
    for (int s = 0; s < 16; ++s) {
        uint32_t a[2][4];
        const float* abase = As + s * 8 + tid4;
#pragma unroll
        for (int mt = 0; mt < 2; ++mt) {
            int r0 = m0 + mt * 16 + gp;
            a[mt][0] = __float_as_uint(abase[r0 * CA_STR]);
            a[mt][1] = __float_as_uint(abase[(r0 + 8) * CA_STR]);
            a[mt][2] = __float_as_uint(abase[r0 * CA_STR + 4]);
            a[mt][3] = __float_as_uint(abase[(r0 + 8) * CA_STR + 4]);
        }
        uint32_t bf[4][2];
        const float* bbase = Bs + (s * 8 + tid4) * CB_STR + n0 + gp;
#pragma unroll
        for (int nt = 0; nt < 4; ++nt) {
            bf[nt][0] = __float_as_uint(bbase[nt * 8]);
            bf[nt][1] = __float_as_uint(bbase[4 * CB_STR + nt * 8]);
        }
#pragma unroll
        for (int mt = 0; mt < 2; ++mt)
#pragma unroll
            for (int nt = 0; nt < 4; ++nt)
                mma_tf32(acc[mt * 4 + nt], a[mt], bf[nt]);
    }

#pragma unroll
    for (int mt = 0; mt < 2; ++mt) {
        int lr0 = m0 + mt * 16 + gp;
        int lr1 = lr0 + 8;
        float iv0 = ivs[lr0], bv0 = bss[lr0];
        float iv1 = ivs[lr1], bv1 = bss[lr1];
        int o0 = o_base + lr0, o1 = o_base + lr1;
        float* d00 = qkv + (size_t)b * 32768 + (o0 & 7) * 4096 + (o0 >> 3) * 128;
        float* d01 = qkv + (size_t)b * 32768 + (o1 & 7) * 4096 + (o1 >> 3) * 128;
#pragma unroll
        for (int nt = 0; nt < 4; ++nt) {
            int d = n0 + nt * 8 + 2 * tid4;
            const float* a4 = acc[mt * 4 + nt];
            float2 s0, s1;
            s0.x = a4[0] * iv0 + bv0; s0.y = a4[1] * iv0 + bv0;
            s1.x = a4[2] * iv1 + bv1; s1.y = a4[3] * iv1 + bv1;
            *reinterpret_cast<float2*>(d00 + d) = s0;
            *reinterpret_cast<float2*>(d01 + d) = s1;
        }
    }
}

// ============================================================================
// Kernel B: attention per (b, h) — round-13 structure + exp2 folding
// smem layout (float units):
//  q [8][128] @0, k [8][128] @1024   (psum/pmax + kvred alias @0 later)
//  vh    half[16][136]  @2048   (1088 floats)
//  relqk f32[16][256]   @3136   (4096; relvh half[16][256] aliases after ph.1)
//  atth  half[128][136] @7232   (8704 floats, ends 15936)
//  outv  f32[16][132]   @15936  (2112, ends 18048)
//  cmax/invs [128]      @18048
// total 18176 floats = 72704 B -> 2 CTAs/SM
// ============================================================================
#define ATH_STR  136
#define VH_STR   136
#define SM_Q     0
#define SM_K     1024
#define SM_VH    2048
#define SM_REL   3136
#define SM_ATTH  7232
#define SM_OUTV  15936
#define SM_CMAX  18048
#define SM_TOTAL 18176

__global__ void __launch_bounds__(256, 2)
attn_kernel(const float* __restrict__ qkv, const float* __restrict__ relative,
            float* __restrict__ out)
{
    extern __shared__ float sm[];
    float*  q     = sm + SM_Q;
    float*  k     = sm + SM_K;
    __half* vh    = reinterpret_cast<__half*>(sm + SM_VH);
    float*  relqk = sm + SM_REL;
    __half* atth  = reinterpret_cast<__half*>(sm + SM_ATTH);
    float*  outv  = sm + SM_OUTV;
    float*  cmax  = sm + SM_CMAX;   // colmax, later invs
    float*  psum  = sm + SM_Q;      // pmax/psum alias q/k
    __half* relvh = reinterpret_cast<__half*>(sm + SM_REL);  // after phase 1

    const int t    = threadIdx.x;
    const int bid  = blockIdx.x;
    const int b    = bid >> 3;
    const int h    = bid & 7;
    const int warp = t >> 5, lane = t & 31;
    const int gp   = lane >> 2, tid4 = lane & 3;
    const uint32_t smb = smem_u32(sm);

    // ---------------- phase 0: load q/k, v (fp16, [i][j]), relqk ---------------
    {
        const float* src = qkv + (size_t)b * 32768 + h * 4096;
#pragma unroll
        for (int it = 0; it < 4; ++it) {
            int e4 = t + 256 * it;
            int r  = e4 >> 5;
            int dw = (e4 & 31) * 4;
            float4 val = *reinterpret_cast<const float4*>(src + r * 128 + dw);
            if (r < 8) {
                *reinterpret_cast<float4*>(q + r * 128 + dw) = val;
            } else if (r < 16) {
                *reinterpret_cast<float4*>(k + (r - 8) * 128 + dw) = val;
            } else {
                int i = r - 16;
                __half2 h01 = __floats2half2_rn(val.x, val.y);
                __half2 h23 = __floats2half2_rn(val.z, val.w);
                uint2 u;
                u.x = *reinterpret_cast<uint32_t*>(&h01);
                u.y = *reinterpret_cast<uint32_t*>(&h23);
                *reinterpret_cast<uint2*>(vh + i * VH_STR + dw) = u;
            }
        }
        for (int idx = t; idx < 16 * 255; idx += 256) {
            int c = idx / 255, m = idx - c * 255;
            float v = relative[idx];
            if (c >= 8) v *= LOG2E;          // k_emb scaled for exp2 folding
            relqk[c * 256 + m] = v;
        }
    }
    __syncthreads();

    // ---------------- phase 1: logits (dots + qr + kr), log2 domain ------------
    const int tx = t & 15, ty = t >> 4;
    const int d0l = tx * 8, j0l = ty * 8;
    ull acc[8][4];
    {
        const int base = d0l - j0l + 120;
#pragma unroll
        for (int a = 0; a < 8; ++a)
#pragma unroll
            for (int p = 0; p < 4; ++p) acc[a][p] = 0ULL;

#pragma unroll 2
        for (int i = 0; i < 8; ++i) {
            const float* qi = q + i * 128;
            const float* ki = k + i * 128;
            ull qp[4], kp[4];
            {
                ulonglong2 a0 = *reinterpret_cast<const ulonglong2*>(qi + d0l);
                ulonglong2 a1 = *reinterpret_cast<const ulonglong2*>(qi + d0l + 4);
                qp[0] = a0.x; qp[1] = a0.y; qp[2] = a1.x; qp[3] = a1.y;
                ulonglong2 b0 = *reinterpret_cast<const ulonglong2*>(ki + d0l);
                ulonglong2 b1 = *reinterpret_cast<const ulonglong2*>(ki + d0l + 4);
                kp[0] = b0.x; kp[1] = b0.y; kp[2] = b1.x; kp[3] = b1.y;
            }
            {
                float kj[8];
                *reinterpret_cast<float4*>(kj)     = *reinterpret_cast<const float4*>(ki + j0l);
                *reinterpret_cast<float4*>(kj + 4) = *reinterpret_cast<const float4*>(ki + j0l + 4);
#pragma unroll
                for (int jj = 0; jj < 8; ++jj) {
                    ull kk2 = pk2(kj[jj], kj[jj]);
#pragma unroll
                    for (int p = 0; p < 4; ++p)
                        acc[jj][p] = fma2(qp[p], kk2, acc[jj][p]);
                }
            }
            {
                float wv[16];
                const float* rr = relqk + i * 256 + base;
#pragma unroll
                for (int u = 0; u < 4; ++u)
                    *reinterpret_cast<float4*>(wv + 4 * u) = *reinterpret_cast<const float4*>(rr + 4 * u);
                ull wo[7];
#pragma unroll
                for (int u = 0; u < 7; ++u) wo[u] = pk2(wv[2 * u + 1], wv[2 * u + 2]);
#pragma unroll
                for (int jj = 0; jj < 8; ++jj)
#pragma unroll
                    for (int p = 0; p < 4; ++p) {
                        const int a = 2 * p + 7 - jj;
                        ull pair = (a & 1) ? wo[a >> 1]
                                           : *reinterpret_cast<const ull*>(wv + a);
                        acc[jj][p] = fma2(qp[p], pair, acc[jj][p]);
                    }
            }
            {
                float wv[16];
                const float* rr = relqk + (8 + i) * 256 + base;
#pragma unroll
                for (int u = 0; u < 4; ++u)
                    *reinterpret_cast<float4*>(wv + 4 * u) = *reinterpret_cast<const float4*>(rr + 4 * u);
                ull wo[7];
#pragma unroll
                for (int u = 0; u < 7; ++u) wo[u] = pk2(wv[2 * u + 1], wv[2 * u + 2]);
#pragma unroll
                for (int jj = 0; jj < 8; ++jj)
#pragma unroll
                    for (int p = 0; p < 4; ++p) {
                        const int a = 2 * p + 7 - jj;
                        ull pair = (a & 1) ? wo[a >> 1]
                                           : *reinterpret_cast<const ull*>(wv + a);
                        acc[jj][p] = fma2(kp[p], pair, acc[jj][p]);
                    }
            }
        }
    }

    // ---------------- phase 1b: column max ladder ------------------------------
    {
        float tmax[8];
#pragma unroll
        for (int dd = 0; dd < 8; ++dd) tmax[dd] = -1e30f;
#pragma unroll
        for (int jj = 0; jj < 8; ++jj)
#pragma unroll
            for (int p = 0; p < 4; ++p) {
                float lo, hi;
                upk2(acc[jj][p], lo, hi);
                tmax[2 * p]     = fmaxf(tmax[2 * p], lo);
                tmax[2 * p + 1] = fmaxf(tmax[2 * p + 1], hi);
            }
        __syncthreads();   // q/k reads done; pmax may overwrite
        float4* pm = reinterpret_cast<float4*>(psum + ty * 128 + d0l);
        pm[0] = make_float4(tmax[0], tmax[1], tmax[2], tmax[3]);
        pm[1] = make_float4(tmax[4], tmax[5], tmax[6], tmax[7]);
    }
    __syncthreads();
    if (t < 128) {
        float m = -1e30f;
#pragma unroll
        for (int r = 0; r < 16; ++r) m = fmaxf(m, psum[r * 128 + t]);
        cmax[t] = m;
    }
    __syncthreads();

    // ---------------- phase 1c: exp2 + fp16 store + sums; relv(fp16) load ------
    {
        float cm[8];
        *reinterpret_cast<float4*>(cm)     = *reinterpret_cast<const float4*>(cmax + d0l);
        *reinterpret_cast<float4*>(cm + 4) = *reinterpret_cast<const float4*>(cmax + d0l + 4);
        float sums[8];
#pragma unroll
        for (int dd = 0; dd < 8; ++dd) sums[dd] = 0.f;
#pragma unroll
        for (int jj = 0; jj < 8; ++jj) {
            __half2 hh[4];
#pragma unroll
            for (int p = 0; p < 4; ++p) {
                float lo, hi;
                upk2(acc[jj][p], lo, hi);
                float e0 = ex2f(lo - cm[2 * p]);
                float e1 = ex2f(hi - cm[2 * p + 1]);
                sums[2 * p]     += e0;
                sums[2 * p + 1] += e1;
                hh[p] = __floats2half2_rn(e0, e1);
            }
            *reinterpret_cast<uint4*>(atth + (j0l + jj) * ATH_STR + d0l) =
                *reinterpret_cast<uint4*>(hh);
        }
        float4* ps = reinterpret_cast<float4*>(psum + ty * 128 + d0l);
        ps[0] = make_float4(sums[0], sums[1], sums[2], sums[3]);
        ps[1] = make_float4(sums[4], sums[5], sums[6], sums[7]);
        // relv fp16 (relqk fully consumed in phase 1)
        for (int idx = t; idx < 16 * 255; idx += 256) {
            int c = idx / 255, m = idx - c * 255;
            relvh[c * 256 + m] = __float2half(relative[16 * 255 + idx]);
        }
    }
    __syncthreads();
    if (t < 128) {
        float s = 0.f;
#pragma unroll
        for (int r = 0; r < 16; ++r) s += psum[r * 128 + t];
        cmax[t] = 1.0f / s;      // cmax now holds invs
    }
    __syncthreads();

    // ---------------- phase 3a: kv Toeplitz (scalar, fp16 relv windows) --------
    const int i0  = (warp & 3) * 4;
    const int jh  = warp >> 2;
    const int d0  = lane * 4;
    ull acco[4][2];
    {
        const int jb0 = jh * 64;
#pragma unroll
        for (int ii = 0; ii < 4; ++ii) { acco[ii][0] = 0ULL; acco[ii][1] = 0ULL; }

        ull we[4][3], wo[4][3];
        float lastf0[4];
#pragma unroll
        for (int ii = 0; ii < 4; ++ii) {
            const __half* rp = relvh + (i0 + ii) * 256 + (d0 - jb0 + 124);
            uint2 uA = *reinterpret_cast<const uint2*>(rp);
            uint2 uB = *reinterpret_cast<const uint2*>(rp + 4);
            float2 fA = __half22float2(*reinterpret_cast<__half2*>(&uA.x));
            float2 fB = __half22float2(*reinterpret_cast<__half2*>(&uA.y));
            float2 fC = __half22float2(*reinterpret_cast<__half2*>(&uB.x));
            float2 fD = __half22float2(*reinterpret_cast<__half2*>(&uB.y));
            we[ii][0] = pk2(fA.x, fA.y);
            we[ii][1] = pk2(fB.x, fB.y);
            we[ii][2] = pk2(fC.x, fC.y);
            wo[ii][0] = pk2(fA.y, fB.x);
            wo[ii][1] = pk2(fB.y, fC.x);
            wo[ii][2] = pk2(fC.y, fD.x);
            lastf0[ii] = fA.x;
        }

        for (int g = 0; g < 16; ++g) {
            const int jb = jb0 + g * 4;
            if (g > 0) {
                const int baseg = d0 - jb + 124;
#pragma unroll
                for (int ii = 0; ii < 4; ++ii) {
                    we[ii][2] = we[ii][0];
                    wo[ii][2] = wo[ii][0];
                    uint2 uu = *reinterpret_cast<const uint2*>(relvh + (i0 + ii) * 256 + baseg);
                    float2 fA = __half22float2(*reinterpret_cast<__half2*>(&uu.x));
                    float2 fB = __half22float2(*reinterpret_cast<__half2*>(&uu.y));
                    we[ii][0] = pk2(fA.x, fA.y);
                    we[ii][1] = pk2(fB.x, fB.y);
                    wo[ii][0] = pk2(fA.y, fB.x);
                    wo[ii][1] = pk2(fB.y, lastf0[ii]);
                    lastf0[ii] = fA.x;
                }
            }
#pragma unroll
            for (int jj = 0; jj < 4; ++jj) {
                const int j = jb + jj;
                uint2 uu = *reinterpret_cast<const uint2*>(atth + j * ATH_STR + d0);
                float2 f01 = __half22float2(*reinterpret_cast<__half2*>(&uu.x));
                float2 f23 = __half22float2(*reinterpret_cast<__half2*>(&uu.y));
                ull atx = pk2(f01.x, f01.y);
                ull aty = pk2(f23.x, f23.y);
#pragma unroll
                for (int ii = 0; ii < 4; ++ii) {
                    const int o0 = 3 - jj;
                    const int o1 = 5 - jj;
                    ull pr0 = (o0 & 1) ? wo[ii][o0 >> 1] : we[ii][o0 >> 1];
                    ull pr1 = (o1 & 1) ? wo[ii][o1 >> 1] : we[ii][o1 >> 1];
                    acco[ii][0] = fma2(atx, pr0, acco[ii][0]);
                    acco[ii][1] = fma2(aty, pr1, acco[ii][1]);
                }
            }
        }

        // jh=1 warps deposit kv partials into kvred (q/k region, dead)
        ull* red = reinterpret_cast<ull*>(sm + SM_Q);
        if (jh == 1) {
#pragma unroll
            for (int ii = 0; ii < 4; ++ii) {
                red[(i0 + ii) * 64 + lane * 2 + 0] = acco[ii][0];
                red[(i0 + ii) * 64 + lane * 2 + 1] = acco[ii][1];
            }
        }
    }

    // ---------------- phase 3b: out_v = attn(fp16) . v(fp16) via HMMA ----------
    {
        const int m0 = warp * 16;                  // 16 d rows per warp
        const uint32_t atth_b = smb + SM_ATTH * 4;
        const uint32_t vh_b   = smb + SM_VH * 4;

        const int arow = (lane & 7) + ((lane >> 4) << 3);        // k-row offset
        const int acol = m0 + (((lane >> 3) & 1) << 3);          // m offset (halves)
        uint32_t a_addr = atth_b + (uint32_t)(arow * ATH_STR + acol) * 2;

        const int bl  = lane & 15;
        const int bn  = bl & 7;
        const int bk8 = ((bl >> 3) & 1) * 8;
        uint32_t b_addr0 = vh_b + (uint32_t)(bn * VH_STR + bk8) * 2;        // i 0..7
        uint32_t b_addr1 = vh_b + (uint32_t)((8 + bn) * VH_STR + bk8) * 2;  // i 8..15

        float c0[4] = {0.f, 0.f, 0.f, 0.f};
        float c1[4] = {0.f, 0.f, 0.f, 0.f};
#pragma unroll
        for (int ks = 0; ks < 8; ++ks) {
            uint32_t a[4];
            ldsm_x4_t(a[0], a[1], a[2], a[3], a_addr + ks * (16 * ATH_STR * 2));
            uint32_t b0[2], b1[2];
            ldsm_x2(b0[0], b0[1], b_addr0 + ks * 32);
            ldsm_x2(b1[0], b1[1], b_addr1 + ks * 32);
            mma_f16(c0, a, b0);
            mma_f16(c1, a, b1);
        }
        // store outv[i][d] (stride 132: conflict-free STS.32)
        const int dA = m0 + gp, dB = m0 + gp + 8;
        outv[(2 * tid4)     * 132 + dA] = c0[0];
        outv[(2 * tid4 + 1) * 132 + dA] = c0[1];
        outv[(2 * tid4)     * 132 + dB] = c0[2];
        outv[(2 * tid4 + 1) * 132 + dB] = c0[3];
        outv[(8 + 2 * tid4)     * 132 + dA] = c1[0];
        outv[(8 + 2 * tid4 + 1) * 132 + dA] = c1[1];
        outv[(8 + 2 * tid4)     * 132 + dB] = c1[2];
        outv[(8 + 2 * tid4 + 1) * 132 + dB] = c1[3];
    }
    __syncthreads();   // kvred + outv complete

    // ---------------- phase 4: combine + normalize + store ---------------------
    if (jh == 0) {
        const ull* red = reinterpret_cast<const ull*>(sm + SM_Q);
        float4 iv4 = *reinterpret_cast<const float4*>(cmax + d0);
        float* ob = out + (size_t)b * 16384 + h * 2048;
#pragma unroll
        for (int ii = 0; ii < 4; ++ii) {
            ull s0 = add2(acco[ii][0], red[(i0 + ii) * 64 + lane * 2 + 0]);
            ull s1 = add2(acco[ii][1], red[(i0 + ii) * 64 + lane * 2 + 1]);
            float4 ov = *reinterpret_cast<const float4*>(outv + (i0 + ii) * 132 + d0);
            float4 r;
            upk2(s0, r.x, r.y);
            upk2(s1, r.z, r.w);
            r.x = (r.x + ov.x) * iv4.x;
            r.y = (r.y + ov.y) * iv4.y;
            r.z = (r.z + ov.z) * iv4.z;
            r.w = (r.w + ov.w) * iv4.w;
            *reinterpret_cast<float4*>(ob + (i0 + ii) * 128 + d0) = r;
        }
    }
}

// ============================================================================
extern "C" void kernel_launch(void* const* d_in, const int* in_sizes, int n_in,
                              void* d_out, int out_size) {
    const float* x        = (const float*)d_in[0];
    const float* W        = (const float*)d_in[1];
    const float* gamma    = (const float*)d_in[2];
    const float* beta     = (const float*)d_in[3];
    const float* mean     = (const float*)d_in[4];
    const float* var      = (const float*)d_in[5];
    const float* relative = (const float*)d_in[6];
    float* out = (float*)d_out;

    int nb = in_sizes[0] / (INC * DIM);

    float* scratch;
    cudaGetSymbolAddress((void**)&scratch, g_qkv);

    const int smemA = CV_TOT * (int)sizeof(float);     // 138240
    const int smemB = SM_TOTAL * (int)sizeof(float);   // 72704
    cudaFuncSetAttribute(conv_bn_mma_kernel, cudaFuncAttributeMaxDynamicSharedMemorySize, smemA);
    cudaFuncSetAttribute(attn_kernel,        cudaFuncAttributeMaxDynamicSharedMemorySize, smemB);

    conv_bn_mma_kernel<<<nb * 2, 512, smemA>>>(x, W, gamma, beta, mean, var, scratch);
    attn_kernel<<<nb * HEADS, 256, smemB>>>(scratch, relative, out);
}

// round 16
// speedup vs baseline: 1.2909x; 1.2909x over previous
#include <cuda_runtime.h>
#include <cuda_fp16.h>
#include <math.h>
#include <stdint.h>

#define HEADS 8
#define DIM 128
#define INC 128
#define EPS 1e-5f
#define QSCALE 0.08838834764831845f   // 128^-0.5
#define LOG2E  1.4426950408889634f

typedef unsigned long long ull;

__device__ float g_qkv[2048 * 32768];   // [b][h][r(0..31)][d]

__device__ __forceinline__ ull pk2(float a, float b) {
    ull r; asm("mov.b64 %0, {%1, %2};" : "=l"(r) : "f"(a), "f"(b)); return r;
}
__device__ __forceinline__ void upk2(ull v, float& a, float& b) {
    asm("mov.b64 {%0, %1}, %2;" : "=f"(a), "=f"(b) : "l"(v));
}
__device__ __forceinline__ ull fma2(ull a, ull b, ull c) {
    ull r; asm("fma.rn.f32x2 %0, %1, %2, %3;" : "=l"(r) : "l"(a), "l"(b), "l"(c));
    return r;
}
__device__ __forceinline__ ull add2(ull a, ull b) {
    ull r; asm("add.rn.f32x2 %0, %1, %2;" : "=l"(r) : "l"(a), "l"(b));
    return r;
}
__device__ __forceinline__ uint32_t f2tf32(float f) {
    uint32_t r; asm("cvt.rna.tf32.f32 %0, %1;" : "=r"(r) : "f"(f)); return r;
}
__device__ __forceinline__ float ex2f(float x) {
    float r; asm("ex2.approx.ftz.f32 %0, %1;" : "=f"(r) : "f"(x)); return r;
}
__device__ __forceinline__ void mma_tf32(float* c, const uint32_t* a, const uint32_t* b) {
    asm volatile(
        "mma.sync.aligned.m16n8k8.row.col.f32.tf32.tf32.f32 "
        "{%0,%1,%2,%3}, {%4,%5,%6,%7}, {%8,%9}, {%0,%1,%2,%3};"
        : "+f"(c[0]), "+f"(c[1]), "+f"(c[2]), "+f"(c[3])
        : "r"(a[0]), "r"(a[1]), "r"(a[2]), "r"(a[3]), "r"(b[0]), "r"(b[1]));
}
__device__ __forceinline__ void mma_f16(float* c, const uint32_t* a, const uint32_t* b) {
    asm volatile(
        "mma.sync.aligned.m16n8k16.row.col.f32.f16.f16.f32 "
        "{%0,%1,%2,%3}, {%4,%5,%6,%7}, {%8,%9}, {%0,%1,%2,%3};"
        : "+f"(c[0]), "+f"(c[1]), "+f"(c[2]), "+f"(c[3])
        : "r"(a[0]), "r"(a[1]), "r"(a[2]), "r"(a[3]), "r"(b[0]), "r"(b[1]));
}
__device__ __forceinline__ void ldsm_x4_t(uint32_t& r0, uint32_t& r1,
                                          uint32_t& r2, uint32_t& r3, uint32_t addr) {
    asm volatile("ldmatrix.sync.aligned.m8n8.x4.trans.shared.b16 {%0,%1,%2,%3}, [%4];"
                 : "=r"(r0), "=r"(r1), "=r"(r2), "=r"(r3) : "r"(addr));
}
__device__ __forceinline__ void ldsm_x2(uint32_t& r0, uint32_t& r1, uint32_t addr) {
    asm volatile("ldmatrix.sync.aligned.m8n8.x2.shared.b16 {%0,%1}, [%2];"
                 : "=r"(r0), "=r"(r1) : "r"(addr));
}
__device__ __forceinline__ uint32_t smem_u32(const void* p) {
    uint32_t a;
    asm("{ .reg .u64 t; cvta.to.shared.u64 t, %1; cvt.u32.u64 %0, t; }"
        : "=r"(a) : "l"(p));
    return a;
}

// ============================================================================
// Kernel A: conv1x1 + BN via mma.sync tf32 (verified) — q rows also x LOG2E
// ============================================================================
#define CA_STR 132
#define CB_STR 136
#define CV_BS  (128 * CA_STR)
#define CV_IV  (CV_BS + 128 * CB_STR)
#define CV_BB  (CV_IV + 128)
#define CV_TOT (CV_BB + 128)

__global__ void __launch_bounds__(512, 1)
conv_bn_mma_kernel(const float* __restrict__ x, const float* __restrict__ W,
                   const float* __restrict__ gamma, const float* __restrict__ beta,
                   const float* __restrict__ mean, const float* __restrict__ var,
                   float* __restrict__ qkv)
{
    extern __shared__ float sm[];
    float* As  = sm;
    float* Bs  = sm + CV_BS;
    float* ivs = sm + CV_IV;
    float* bss = sm + CV_BB;

    const int t      = threadIdx.x;
    const int b      = blockIdx.x >> 1;
    const int o_base = (blockIdx.x & 1) * 128;

#pragma unroll
    for (int it = 0; it < 8; ++it) {
        int e  = t + 512 * it;
        int o  = e >> 5;
        int c4 = (e & 31) * 4;
        float4 wv = *reinterpret_cast<const float4*>(W + (o_base + o) * 128 + c4);
        float4 s;
        s.x = __uint_as_float(f2tf32(wv.x));
        s.y = __uint_as_float(f2tf32(wv.y));
        s.z = __uint_as_float(f2tf32(wv.z));
        s.w = __uint_as_float(f2tf32(wv.w));
        *reinterpret_cast<float4*>(As + o * CA_STR + c4) = s;
    }
#pragma unroll
    for (int it = 0; it < 8; ++it) {
        int e  = t + 512 * it;
        int c  = e >> 5;
        int d4 = (e & 31) * 4;
        float4 xv = *reinterpret_cast<const float4*>(x + (size_t)b * 16384 + c * 128 + d4);
        float4 s;
        s.x = __uint_as_float(f2tf32(xv.x));
        s.y = __uint_as_float(f2tf32(xv.y));
        s.z = __uint_as_float(f2tf32(xv.z));
        s.w = __uint_as_float(f2tf32(xv.w));
        *reinterpret_cast<float4*>(Bs + c * CB_STR + d4) = s;
    }
    if (t < 128) {
        int o = o_base + t;
        float iv   = gamma[o] * rsqrtf(var[o] + EPS);
        float bias = beta[o] - mean[o] * iv;
        if (o < 64) { iv *= QSCALE * LOG2E; bias *= QSCALE * LOG2E; }
        ivs[t] = iv;
        bss[t] = bias;
    }
    __syncthreads();

    const int warp = t >> 5, lane = t & 31;
    const int wm = warp & 3, wn = warp >> 2;
    const int m0 = wm * 32, n0 = wn * 32;
    const int gp = lane >> 2, tid4 = lane & 3;

    float acc[8][4];
#pragma unroll
    for (int i = 0; i < 8; ++i)
#pragma unroll
        for (int p = 0; p < 4; ++p) acc[i][p] = 0.f;

#pragma unroll
    for (int s = 0; s < 16; ++s) {
        uint32_t a[2][4];
        const float* abase = As + s * 8 + tid4;
#pragma unroll
        for (int mt = 0; mt < 2; ++mt) {
            int r0 = m0 + mt * 16 + gp;
            a[mt][0] = __float_as_uint(abase[r0 * CA_STR]);
            a[mt][1] = __float_as_uint(abase[(r0 + 8) * CA_STR]);
            a[mt][2] = __float_as_uint(abase[r0 * CA_STR + 4]);
            a[mt][3] = __float_as_uint(abase[(r0 + 8) * CA_STR + 4]);
        }
        uint32_t bf[4][2];
        const float* bbase = Bs + (s * 8 + tid4) * CB_STR + n0 + gp;
#pragma unroll
        for (int nt = 0; nt < 4; ++nt) {
            bf[nt][0] = __float_as_uint(bbase[nt * 8]);
            bf[nt][1] = __float_as_uint(bbase[4 * CB_STR + nt * 8]);
        }
#pragma unroll
        for (int mt = 0; mt < 2; ++mt)
#pragma unroll
            for (int nt = 0; nt < 4; ++nt)
                mma_tf32(acc[mt * 4 + nt], a[mt], bf[nt]);
    }

#pragma unroll
    for (int mt = 0; mt < 2; ++mt) {
        int lr0 = m0 + mt * 16 + gp;
        int lr1 = lr0 + 8;
        float iv0 = ivs[lr0], bv0 = bss[lr0];
        float iv1 = ivs[lr1], bv1 = bss[lr1];
        int o0 = o_base + lr0, o1 = o_base + lr1;
        float* d00 = qkv + (size_t)b * 32768 + (o0 & 7) * 4096 + (o0 >> 3) * 128;
        float* d01 = qkv + (size_t)b * 32768 + (o1 & 7) * 4096 + (o1 >> 3) * 128;
#pragma unroll
        for (int nt = 0; nt < 4; ++nt) {
            int d = n0 + nt * 8 + 2 * tid4;
            const float* a4 = acc[mt * 4 + nt];
            float2 s0, s1;
            s0.x = a4[0] * iv0 + bv0; s0.y = a4[1] * iv0 + bv0;
            s1.x = a4[2] * iv1 + bv1; s1.y = a4[3] * iv1 + bv1;
            *reinterpret_cast<float2*>(d00 + d) = s0;
            *reinterpret_cast<float2*>(d01 + d) = s1;
        }
    }
}

// ============================================================================
// Kernel B: attention per (b, h) — round-13 structure + exp2 folding
// smem layout (float units):
//  q [8][128] @0, k [8][128] @1024   (psum/pmax + kvred alias @0 later)
//  vh    half[16][136]  @2048   (1088 floats)
//  relqk f32[16][256]   @3136   (4096; relvh half[16][256] aliases after ph.1)
//  atth  half[128][136] @7232   (8704 floats, ends 15936)
//  outv  f32[16][132]   @15936  (2112, ends 18048)
//  cmax/invs [128]      @18048
// total 18176 floats = 72704 B -> 2 CTAs/SM
// ============================================================================
#define ATH_STR  136
#define VH_STR   136
#define SM_Q     0
#define SM_K     1024
#define SM_VH    2048
#define SM_REL   3136
#define SM_ATTH  7232
#define SM_OUTV  15936
#define SM_CMAX  18048
#define SM_TOTAL 18176

__global__ void __launch_bounds__(256, 2)
attn_kernel(const float* __restrict__ qkv, const float* __restrict__ relative,
            float* __restrict__ out)
{
    extern __shared__ float sm[];
    float*  q     = sm + SM_Q;
    float*  k     = sm + SM_K;
    __half* vh    = reinterpret_cast<__half*>(sm + SM_VH);
    float*  relqk = sm + SM_REL;
    __half* atth  = reinterpret_cast<__half*>(sm + SM_ATTH);
    float*  outv  = sm + SM_OUTV;
    float*  cmax  = sm + SM_CMAX;   // colmax, later invs
    float*  psum  = sm + SM_Q;      // pmax/psum alias q/k
    __half* relvh = reinterpret_cast<__half*>(sm + SM_REL);  // after phase 1

    const int t    = threadIdx.x;
    const int bid  = blockIdx.x;
    const int b    = bid >> 3;
    const int h    = bid & 7;
    const int warp = t >> 5, lane = t & 31;
    const int gp   = lane >> 2, tid4 = lane & 3;
    const uint32_t smb = smem_u32(sm);

    // ---------------- phase 0: load q/k, v (fp16, [i][j]), relqk ---------------
    {
        const float* src = qkv + (size_t)b * 32768 + h * 4096;
#pragma unroll
        for (int it = 0; it < 4; ++it) {
            int e4 = t + 256 * it;
            int r  = e4 >> 5;
            int dw = (e4 & 31) * 4;
            float4 val = *reinterpret_cast<const float4*>(src + r * 128 + dw);
            if (r < 8) {
                *reinterpret_cast<float4*>(q + r * 128 + dw) = val;
            } else if (r < 16) {
                *reinterpret_cast<float4*>(k + (r - 8) * 128 + dw) = val;
            } else {
                int i = r - 16;
                __half2 h01 = __floats2half2_rn(val.x, val.y);
                __half2 h23 = __floats2half2_rn(val.z, val.w);
                uint2 u;
                u.x = *reinterpret_cast<uint32_t*>(&h01);
                u.y = *reinterpret_cast<uint32_t*>(&h23);
                *reinterpret_cast<uint2*>(vh + i * VH_STR + dw) = u;
            }
        }
        for (int idx = t; idx < 16 * 255; idx += 256) {
            int c = idx / 255, m = idx - c * 255;
            float v = relative[idx];
            if (c >= 8) v *= LOG2E;          // k_emb scaled for exp2 folding
            relqk[c * 256 + m] = v;
        }
    }
    __syncthreads();

    // ---------------- phase 1: logits (dots + qr + kr), log2 domain ------------
    const int tx = t & 15, ty = t >> 4;
    const int d0l = tx * 8, j0l = ty * 8;
    ull acc[8][4];
    {
        const int base = d0l - j0l + 120;
#pragma unroll
        for (int a = 0; a < 8; ++a)
#pragma unroll
            for (int p = 0; p < 4; ++p) acc[a][p] = 0ULL;

#pragma unroll 2
        for (int i = 0; i < 8; ++i) {
            const float* qi = q + i * 128;
            const float* ki = k + i * 128;
            ull qp[4], kp[4];
            {
                ulonglong2 a0 = *reinterpret_cast<const ulonglong2*>(qi + d0l);
                ulonglong2 a1 = *reinterpret_cast<const ulonglong2*>(qi + d0l + 4);
                qp[0] = a0.x; qp[1] = a0.y; qp[2] = a1.x; qp[3] = a1.y;
                ulonglong2 b0 = *reinterpret_cast<const ulonglong2*>(ki + d0l);
                ulonglong2 b1 = *reinterpret_cast<const ulonglong2*>(ki + d0l + 4);
                kp[0] = b0.x; kp[1] = b0.y; kp[2] = b1.x; kp[3] = b1.y;
            }
            {
                float kj[8];
                *reinterpret_cast<float4*>(kj)     = *reinterpret_cast<const float4*>(ki + j0l);
                *reinterpret_cast<float4*>(kj + 4) = *reinterpret_cast<const float4*>(ki + j0l + 4);
#pragma unroll
                for (int jj = 0; jj < 8; ++jj) {
                    ull kk2 = pk2(kj[jj], kj[jj]);
#pragma unroll
                    for (int p = 0; p < 4; ++p)
                        acc[jj][p] = fma2(qp[p], kk2, acc[jj][p]);
                }
            }
            {
                float wv[16];
                const float* rr = relqk + i * 256 + base;
#pragma unroll
                for (int u = 0; u < 4; ++u)
                    *reinterpret_cast<float4*>(wv + 4 * u) = *reinterpret_cast<const float4*>(rr + 4 * u);
                ull wo[7];
#pragma unroll
                for (int u = 0; u < 7; ++u) wo[u] = pk2(wv[2 * u + 1], wv[2 * u + 2]);
#pragma unroll
                for (int jj = 0; jj < 8; ++jj)
#pragma unroll
                    for (int p = 0; p < 4; ++p) {
                        const int a = 2 * p + 7 - jj;
                        ull pair = (a & 1) ? wo[a >> 1]
                                           : *reinterpret_cast<const ull*>(wv + a);
                        acc[jj][p] = fma2(qp[p], pair, acc[jj][p]);
                    }
            }
            {
                float wv[16];
                const float* rr = relqk + (8 + i) * 256 + base;
#pragma unroll
                for (int u = 0; u < 4; ++u)
                    *reinterpret_cast<float4*>(wv + 4 * u) = *reinterpret_cast<const float4*>(rr + 4 * u);
                ull wo[7];
#pragma unroll
                for (int u = 0; u < 7; ++u) wo[u] = pk2(wv[2 * u + 1], wv[2 * u + 2]);
#pragma unroll
                for (int jj = 0; jj < 8; ++jj)
#pragma unroll
                    for (int p = 0; p < 4; ++p) {
                        const int a = 2 * p + 7 - jj;
                        ull pair = (a & 1) ? wo[a >> 1]
                                           : *reinterpret_cast<const ull*>(wv + a);
                        acc[jj][p] = fma2(kp[p], pair, acc[jj][p]);
                    }
            }
        }
    }

    // ---------------- phase 1b: column max ladder ------------------------------
    {
        float tmax[8];
#pragma unroll
        for (int dd = 0; dd < 8; ++dd) tmax[dd] = -1e30f;
#pragma unroll
        for (int jj = 0; jj < 8; ++jj)
#pragma unroll
            for (int p = 0; p < 4; ++p) {
                float lo, hi;
                upk2(acc[jj][p], lo, hi);
                tmax[2 * p]     = fmaxf(tmax[2 * p], lo);
                tmax[2 * p + 1] = fmaxf(tmax[2 * p + 1], hi);
            }
        __syncthreads();   // q/k reads done; pmax may overwrite
        float4* pm = reinterpret_cast<float4*>(psum + ty * 128 + d0l);
        pm[0] = make_float4(tmax[0], tmax[1], tmax[2], tmax[3]);
        pm[1] = make_float4(tmax[4], tmax[5], tmax[6], tmax[7]);
    }
    __syncthreads();
    if (t < 128) {
        float m = -1e30f;
#pragma unroll
        for (int r = 0; r < 16; ++r) m = fmaxf(m, psum[r * 128 + t]);
        cmax[t] = m;
    }
    __syncthreads();

    // ---------------- phase 1c: exp2 + fp16 store + sums; relv(fp16) load ------
    {
        float cm[8];
        *reinterpret_cast<float4*>(cm)     = *reinterpret_cast<const float4*>(cmax + d0l);
        *reinterpret_cast<float4*>(cm + 4) = *reinterpret_cast<const float4*>(cmax + d0l + 4);
        float sums[8];
#pragma unroll
        for (int dd = 0; dd < 8; ++dd) sums[dd] = 0.f;
#pragma unroll
        for (int jj = 0; jj < 8; ++jj) {
            __half2 hh[4];
#pragma unroll
            for (int p = 0; p < 4; ++p) {
                float lo, hi;
                upk2(acc[jj][p], lo, hi);
                float e0 = ex2f(lo - cm[2 * p]);
                float e1 = ex2f(hi - cm[2 * p + 1]);
                sums[2 * p]     += e0;
                sums[2 * p + 1] += e1;
                hh[p] = __floats2half2_rn(e0, e1);
            }
            *reinterpret_cast<uint4*>(atth + (j0l + jj) * ATH_STR + d0l) =
                *reinterpret_cast<uint4*>(hh);
        }
        float4* ps = reinterpret_cast<float4*>(psum + ty * 128 + d0l);
        ps[0] = make_float4(sums[0], sums[1], sums[2], sums[3]);
        ps[1] = make_float4(sums[4], sums[5], sums[6], sums[7]);
        // relv fp16 (relqk fully consumed in phase 1)
        for (int idx = t; idx < 16 * 255; idx += 256) {
            int c = idx / 255, m = idx - c * 255;
            relvh[c * 256 + m] = __float2half(relative[16 * 255 + idx]);
        }
    }
    __syncthreads();
    if (t < 128) {
        float s = 0.f;
#pragma unroll
        for (int r = 0; r < 16; ++r) s += psum[r * 128 + t];
        cmax[t] = 1.0f / s;      // cmax now holds invs
    }
    __syncthreads();

    // ---------------- phase 3a: kv Toeplitz (scalar, fp16 relv windows) --------
    const int i0  = (warp & 3) * 4;
    const int jh  = warp >> 2;
    const int d0  = lane * 4;
    ull acco[4][2];
    {
        const int jb0 = jh * 64;
#pragma unroll
        for (int ii = 0; ii < 4; ++ii) { acco[ii][0] = 0ULL; acco[ii][1] = 0ULL; }

        ull we[4][3], wo[4][3];
        float lastf0[4];
#pragma unroll
        for (int ii = 0; ii < 4; ++ii) {
            const __half* rp = relvh + (i0 + ii) * 256 + (d0 - jb0 + 124);
            uint2 uA = *reinterpret_cast<const uint2*>(rp);
            uint2 uB = *reinterpret_cast<const uint2*>(rp + 4);
            float2 fA = __half22float2(*reinterpret_cast<__half2*>(&uA.x));
            float2 fB = __half22float2(*reinterpret_cast<__half2*>(&uA.y));
            float2 fC = __half22float2(*reinterpret_cast<__half2*>(&uB.x));
            float2 fD = __half22float2(*reinterpret_cast<__half2*>(&uB.y));
            we[ii][0] = pk2(fA.x, fA.y);
            we[ii][1] = pk2(fB.x, fB.y);
            we[ii][2] = pk2(fC.x, fC.y);
            wo[ii][0] = pk2(fA.y, fB.x);
            wo[ii][1] = pk2(fB.y, fC.x);
            wo[ii][2] = pk2(fC.y, fD.x);
            lastf0[ii] = fA.x;
        }

        for (int g = 0; g < 16; ++g) {
            const int jb = jb0 + g * 4;
            if (g > 0) {
                const int baseg = d0 - jb + 124;
#pragma unroll
                for (int ii = 0; ii < 4; ++ii) {
                    we[ii][2] = we[ii][0];
                    wo[ii][2] = wo[ii][0];
                    uint2 uu = *reinterpret_cast<const uint2*>(relvh + (i0 + ii) * 256 + baseg);
                    float2 fA = __half22float2(*reinterpret_cast<__half2*>(&uu.x));
                    float2 fB = __half22float2(*reinterpret_cast<__half2*>(&uu.y));
                    we[ii][0] = pk2(fA.x, fA.y);
                    we[ii][1] = pk2(fB.x, fB.y);
                    wo[ii][0] = pk2(fA.y, fB.x);
                    wo[ii][1] = pk2(fB.y, lastf0[ii]);
                    lastf0[ii] = fA.x;
                }
            }
#pragma unroll
            for (int jj = 0; jj < 4; ++jj) {
                const int j = jb + jj;
                uint2 uu = *reinterpret_cast<const uint2*>(atth + j * ATH_STR + d0);
                float2 f01 = __half22float2(*reinterpret_cast<__half2*>(&uu.x));
                float2 f23 = __half22float2(*reinterpret_cast<__half2*>(&uu.y));
                ull atx = pk2(f01.x, f01.y);
                ull aty = pk2(f23.x, f23.y);
#pragma unroll
                for (int ii = 0; ii < 4; ++ii) {
                    const int o0 = 3 - jj;
                    const int o1 = 5 - jj;
                    ull pr0 = (o0 & 1) ? wo[ii][o0 >> 1] : we[ii][o0 >> 1];
                    ull pr1 = (o1 & 1) ? wo[ii][o1 >> 1] : we[ii][o1 >> 1];
                    acco[ii][0] = fma2(atx, pr0, acco[ii][0]);
                    acco[ii][1] = fma2(aty, pr1, acco[ii][1]);
                }
            }
        }

        // jh=1 warps deposit kv partials into kvred (q/k region, dead)
        ull* red = reinterpret_cast<ull*>(sm + SM_Q);
        if (jh == 1) {
#pragma unroll
            for (int ii = 0; ii < 4; ++ii) {
                red[(i0 + ii) * 64 + lane * 2 + 0] = acco[ii][0];
                red[(i0 + ii) * 64 + lane * 2 + 1] = acco[ii][1];
            }
        }
    }

    // ---------------- phase 3b: out_v = attn(fp16) . v(fp16) via HMMA ----------
    {
        const int m0 = warp * 16;                  // 16 d rows per warp
        const uint32_t atth_b = smb + SM_ATTH * 4;
        const uint32_t vh_b   = smb + SM_VH * 4;

        const int arow = (lane & 7) + ((lane >> 4) << 3);        // k-row offset
        const int acol = m0 + (((lane >> 3) & 1) << 3);          // m offset (halves)
        uint32_t a_addr = atth_b + (uint32_t)(arow * ATH_STR + acol) * 2;

        const int bl  = lane & 15;
        const int bn  = bl & 7;
        const int bk8 = ((bl >> 3) & 1) * 8;
        uint32_t b_addr0 = vh_b + (uint32_t)(bn * VH_STR + bk8) * 2;        // i 0..7
        uint32_t b_addr1 = vh_b + (uint32_t)((8 + bn) * VH_STR + bk8) * 2;  // i 8..15

        float c0[4] = {0.f, 0.f, 0.f, 0.f};
        float c1[4] = {0.f, 0.f, 0.f, 0.f};
#pragma unroll
        for (int ks = 0; ks < 8; ++ks) {
            uint32_t a[4];
            ldsm_x4_t(a[0], a[1], a[2], a[3], a_addr + ks * (16 * ATH_STR * 2));
            uint32_t b0[2], b1[2];
            ldsm_x2(b0[0], b0[1], b_addr0 + ks * 32);
            ldsm_x2(b1[0], b1[1], b_addr1 + ks * 32);
            mma_f16(c0, a, b0);
            mma_f16(c1, a, b1);
        }
        // store outv[i][d] (stride 132: conflict-free STS.32)
        const int dA = m0 + gp, dB = m0 + gp + 8;
        outv[(2 * tid4)     * 132 + dA] = c0[0];
        outv[(2 * tid4 + 1) * 132 + dA] = c0[1];
        outv[(2 * tid4)     * 132 + dB] = c0[2];
        outv[(2 * tid4 + 1) * 132 + dB] = c0[3];
        outv[(8 + 2 * tid4)     * 132 + dA] = c1[0];
        outv[(8 + 2 * tid4 + 1) * 132 + dA] = c1[1];
        outv[(8 + 2 * tid4)     * 132 + dB] = c1[2];
        outv[(8 + 2 * tid4 + 1) * 132 + dB] = c1[3];
    }
    __syncthreads();   // kvred + outv complete

    // ---------------- phase 4: combine + normalize + store ---------------------
    if (jh == 0) {
        const ull* red = reinterpret_cast<const ull*>(sm + SM_Q);
        float4 iv4 = *reinterpret_cast<const float4*>(cmax + d0);
        float* ob = out + (size_t)b * 16384 + h * 2048;
#pragma unroll
        for (int ii = 0; ii < 4; ++ii) {
            ull s0 = add2(acco[ii][0], red[(i0 + ii) * 64 + lane * 2 + 0]);
            ull s1 = add2(acco[ii][1], red[(i0 + ii) * 64 + lane * 2 + 1]);
            float4 ov = *reinterpret_cast<const float4*>(outv + (i0 + ii) * 132 + d0);
            float4 r;
            upk2(s0, r.x, r.y);
            upk2(s1, r.z, r.w);
            r.x = (r.x + ov.x) * iv4.x;
            r.y = (r.y + ov.y) * iv4.y;
            r.z = (r.z + ov.z) * iv4.z;
            r.w = (r.w + ov.w) * iv4.w;
            *reinterpret_cast<float4*>(ob + (i0 + ii) * 128 + d0) = r;
        }
    }
}

// ============================================================================
extern "C" void kernel_launch(void* const* d_in, const int* in_sizes, int n_in,
                              void* d_out, int out_size) {
    const float* x        = (const float*)d_in[0];
    const float* W        = (const float*)d_in[1];
    const float* gamma    = (const float*)d_in[2];
    const float* beta     = (const float*)d_in[3];
    const float* mean     = (const float*)d_in[4];
    const float* var      = (const float*)d_in[5];
    const float* relative = (const float*)d_in[6];
    float* out = (float*)d_out;

    int nb = in_sizes[0] / (INC * DIM);

    float* scratch;
    cudaGetSymbolAddress((void**)&scratch, g_qkv);

    const int smemA = CV_TOT * (int)sizeof(float);     // 138240
    const int smemB = SM_TOTAL * (int)sizeof(float);   // 72704
    cudaFuncSetAttribute(conv_bn_mma_kernel, cudaFuncAttributeMaxDynamicSharedMemorySize, smemA);
    cudaFuncSetAttribute(attn_kernel,        cudaFuncAttributeMaxDynamicSharedMemorySize, smemB);

    conv_bn_mma_kernel<<<nb * 2, 512, smemA>>>(x, W, gamma, beta, mean, var, scratch);
    attn_kernel<<<nb * HEADS, 256, smemB>>>(scratch, relative, out);
}